// round 2
// baseline (speedup 1.0000x reference)
#include <cuda_runtime.h>
#include <math.h>

#define BATCH   16
#define HH      512
#define WW      512
#define NPIX    (HH*WW)
#define KK      50
#define NITERS  10

#define TDIM    32            // 32x32 pixel tile per block
#define PIXPT   4             // pixels per thread (along x)
#define THREADS 256
#define TILES   (WW/TDIM)     // 16

__device__ float  g_centers[BATCH][KK][5];
__device__ double g_sums[BATCH][KK][6];   // r,g,b, y*ratio, x*ratio, count

__device__ __forceinline__ float ratiof() {
    // COMPACTNESS / sqrt(N/K), rounded to f32 exactly like the reference
    return (float)(10.0 / sqrt((double)NPIX / (double)KK));
}

// -------------------------------------------------------------------------
// Init: grid-sampled centers (n=8 grid, first 50), zero segment sums.
// -------------------------------------------------------------------------
__global__ void k_init(const float* __restrict__ X) {
    int img = blockIdx.x;
    int t   = threadIdx.x;
    double* s = &g_sums[img][0][0];
    for (int i = t; i < KK*6; i += blockDim.x) s[i] = 0.0;
    if (t < KK) {
        const float R = ratiof();
        int gi = t >> 3, gj = t & 7;
        int y = 64*gi + 32, x = 64*gj + 32;
        size_t base = ((size_t)(img*3)*HH + y) * WW + x;
        g_centers[img][t][0] = X[base];
        g_centers[img][t][1] = X[base + (size_t)HH*WW];
        g_centers[img][t][2] = X[base + 2*(size_t)HH*WW];
        g_centers[img][t][3] = (float)y * R;
        g_centers[img][t][4] = (float)x * R;
    }
}

// -------------------------------------------------------------------------
// Fused assignment + segment accumulation, with provably-safe spatial
// candidate pruning per tile. Distance formula replicates the reference:
//   d = f2 + c2 - 2*dot   (argmin, first-index tie-break)
// -------------------------------------------------------------------------
__global__ void __launch_bounds__(THREADS) k_assign(const float* __restrict__ X) {
    const int img = blockIdx.z;
    const int x0  = blockIdx.x * TDIM;
    const int y0  = blockIdx.y * TDIM;
    const int t   = threadIdx.x;
    const float R = ratiof();

    __shared__ float sC[KK][5];
    __shared__ float sC2[KK];
    __shared__ float sLB[KK];
    __shared__ float sUB[KK];
    __shared__ float sAcc[KK][6];
    __shared__ int   sCand[KK];
    __shared__ int   sNum;

    for (int i = t; i < KK*5; i += THREADS)
        (&sC[0][0])[i] = (&g_centers[img][0][0])[i];
    for (int i = t; i < KK*6; i += THREADS)
        (&sAcc[0][0])[i] = 0.0f;
    __syncthreads();

    if (t < KK) {
        float c0=sC[t][0], c1=sC[t][1], c2=sC[t][2], c3=sC[t][3], c4=sC[t][4];
        sC2[t] = (((c0*c0 + c1*c1) + c2*c2) + c3*c3) + c4*c4;
        float ya = (float)y0 * R;
        float yb = (float)(y0 + TDIM - 1) * R;
        float xa = (float)x0 * R;
        float xb = (float)(x0 + TDIM - 1) * R;
        float dymin = fmaxf(fmaxf(ya - c3, c3 - yb), 0.0f);
        float dxmin = fmaxf(fmaxf(xa - c4, c4 - xb), 0.0f);
        float dymax = fmaxf(fabsf(ya - c3), fabsf(yb - c3));
        float dxmax = fmaxf(fabsf(xa - c4), fabsf(xb - c4));
        sLB[t] = dymin*dymin + dxmin*dxmin;              // >= 0, color >= 0
        sUB[t] = dymax*dymax + dxmax*dxmax + 3.0f;       // + color max (<=3)
    }
    __syncthreads();
    if (t == 0) {
        float m = sUB[0];
        #pragma unroll
        for (int j = 1; j < KK; j++) m = fminf(m, sUB[j]);
        m += 1.0f;  // slack >> fp32 rounding of the distance formula
        int n = 0;
        for (int j = 0; j < KK; j++)
            if (sLB[j] <= m) sCand[n++] = j;             // ascending index order
        sNum = n;
    }
    __syncthreads();
    const int num = sNum;

    const int ty = t >> 3;
    const int xo = x0 + (t & 7) * PIXPT;
    const int y  = y0 + ty;
    const float ys = (float)y * R;

    size_t base = ((size_t)(img*3)*HH + y) * WW + xo;
    float4 r4 = *reinterpret_cast<const float4*>(X + base);
    float4 g4 = *reinterpret_cast<const float4*>(X + base + (size_t)HH*WW);
    float4 b4 = *reinterpret_cast<const float4*>(X + base + 2*(size_t)HH*WW);

    float rv[PIXPT] = {r4.x, r4.y, r4.z, r4.w};
    float gv[PIXPT] = {g4.x, g4.y, g4.z, g4.w};
    float bv[PIXPT] = {b4.x, b4.y, b4.z, b4.w};
    float xs[PIXPT], f2[PIXPT], best[PIXPT];
    int   bj[PIXPT];
    #pragma unroll
    for (int i = 0; i < PIXPT; i++) {
        xs[i]   = (float)(xo + i) * R;
        f2[i]   = (((rv[i]*rv[i] + gv[i]*gv[i]) + bv[i]*bv[i]) + ys*ys) + xs[i]*xs[i];
        best[i] = 3.0e38f;
        bj[i]   = 0;
    }

    for (int c = 0; c < num; c++) {
        int j = sCand[c];
        float c0=sC[j][0], c1=sC[j][1], c2=sC[j][2], c3=sC[j][3], c4=sC[j][4];
        float cc = sC2[j];
        #pragma unroll
        for (int i = 0; i < PIXPT; i++) {
            float dot = rv[i]*c0 + gv[i]*c1 + bv[i]*c2 + ys*c3 + xs[i]*c4;
            float v = (f2[i] + cc) - 2.0f*dot;
            if (v < best[i]) { best[i] = v; bj[i] = j; }   // strict <: first index wins
        }
    }

    // Run-length accumulation (labels are spatially coherent) into shared
    int   cur = bj[0];
    float aR=rv[0], aG=gv[0], aB=bv[0], aX=xs[0], aC=1.0f;
    #pragma unroll
    for (int i = 1; i < PIXPT; i++) {
        if (bj[i] == cur) { aR+=rv[i]; aG+=gv[i]; aB+=bv[i]; aX+=xs[i]; aC+=1.0f; }
        else {
            atomicAdd(&sAcc[cur][0], aR); atomicAdd(&sAcc[cur][1], aG);
            atomicAdd(&sAcc[cur][2], aB); atomicAdd(&sAcc[cur][3], ys*aC);
            atomicAdd(&sAcc[cur][4], aX); atomicAdd(&sAcc[cur][5], aC);
            cur = bj[i]; aR=rv[i]; aG=gv[i]; aB=bv[i]; aX=xs[i]; aC=1.0f;
        }
    }
    atomicAdd(&sAcc[cur][0], aR); atomicAdd(&sAcc[cur][1], aG);
    atomicAdd(&sAcc[cur][2], aB); atomicAdd(&sAcc[cur][3], ys*aC);
    atomicAdd(&sAcc[cur][4], aX); atomicAdd(&sAcc[cur][5], aC);

    __syncthreads();
    // Flush only candidate clusters (others provably untouched); double atomics
    for (int i = t; i < num*6; i += THREADS) {
        int ci = i / 6, d = i - ci*6;
        int j = sCand[ci];
        atomicAdd(&g_sums[img][j][d], (double)sAcc[j][d]);
    }
}

// -------------------------------------------------------------------------
// Center update: new_center = sums / max(count, 1); re-zero sums.
// -------------------------------------------------------------------------
__global__ void k_update() {
    int img = blockIdx.x;
    int t   = threadIdx.x;
    if (t < KK) {
        double cnt = g_sums[img][t][5];
        double m = fmax(cnt, 1.0);
        #pragma unroll
        for (int d = 0; d < 5; d++) {
            g_centers[img][t][d] = (float)(g_sums[img][t][d] / m);
            g_sums[img][t][d] = 0.0;
        }
        g_sums[img][t][5] = 0.0;
    }
}

// -------------------------------------------------------------------------
// Finalize: mean_rgb[c] = (1/N) * sum_seg segsum_c / max(cnt,1); then k.
// All-double for a near-exact result. Re-zeroes g_sums for graph replay.
// -------------------------------------------------------------------------
__global__ void k_final(float* __restrict__ out) {
    int img = blockIdx.x;
    int t   = threadIdx.x;
    __shared__ double sr[KK], sg[KK], sb[KK];
    if (t < KK) {
        double cnt = g_sums[img][t][5];
        double m = fmax(cnt, 1.0);
        sr[t] = g_sums[img][t][0] / m;
        sg[t] = g_sums[img][t][1] / m;
        sb[t] = g_sums[img][t][2] / m;
        #pragma unroll
        for (int d = 0; d < 6; d++) g_sums[img][t][d] = 0.0;
    }
    __syncthreads();
    if (t == 0) {
        double tr=0.0, tg=0.0, tb=0.0;
        for (int j = 0; j < KK; j++) { tr += sr[j]; tg += sg[j]; tb += sb[j]; }
        const double invN = 1.0 / (double)NPIX;
        double mr = tr * invN, mg = tg * invN, mb = tb * invN;
        double Drg = (mr-mg)*(mr-mg);
        double Drb = (mr-mb)*(mr-mb);
        double Dgb = (mb-mg)*(mb-mg);
        out[img] = (float)sqrt(Drg*Drg + Drb*Drb + Dgb*Dgb);
    }
}

// -------------------------------------------------------------------------
extern "C" void kernel_launch(void* const* d_in, const int* in_sizes, int n_in,
                              void* d_out, int out_size) {
    const float* X = (const float*)d_in[0];
    float* out = (float*)d_out;

    k_init<<<BATCH, 64>>>(X);
    dim3 grid(TILES, TILES, BATCH);
    for (int it = 0; it < NITERS; it++) {
        k_assign<<<grid, THREADS>>>(X);
        k_update<<<BATCH, 64>>>();
    }
    k_assign<<<grid, THREADS>>>(X);   // final labels + segment sums
    k_final<<<BATCH, 64>>>(out);
}

// round 3
// speedup vs baseline: 7.2223x; 7.2223x over previous
#include <cuda_runtime.h>
#include <math.h>

#define BATCH   16
#define HH      512
#define WW      512
#define NPIX    (HH*WW)
#define KK      50
#define NITERS  10

#define TDIM    32            // 32x32 pixel tile per block
#define PIXPT   4             // pixels per thread (along x)
#define THREADS 256
#define TILES   (WW/TDIM)     // 16

__device__ float  g_centers[BATCH][KK][5];
__device__ double g_sums[BATCH][KK][6];   // r,g,b, y*ratio, x*ratio, count

__device__ __forceinline__ float ratiof() {
    // COMPACTNESS / sqrt(N/K), rounded to f32 exactly like the reference
    return (float)(10.0 / sqrt((double)NPIX / (double)KK));
}

// -------------------------------------------------------------------------
// Init: grid-sampled centers (n=8 grid, first 50), zero segment sums.
// -------------------------------------------------------------------------
__global__ void k_init(const float* __restrict__ X) {
    int img = blockIdx.x;
    int t   = threadIdx.x;
    double* s = &g_sums[img][0][0];
    for (int i = t; i < KK*6; i += blockDim.x) s[i] = 0.0;
    if (t < KK) {
        const float R = ratiof();
        int gi = t >> 3, gj = t & 7;
        int y = 64*gi + 32, x = 64*gj + 32;
        size_t base = ((size_t)(img*3)*HH + y) * WW + x;
        g_centers[img][t][0] = X[base];
        g_centers[img][t][1] = X[base + (size_t)HH*WW];
        g_centers[img][t][2] = X[base + 2*(size_t)HH*WW];
        g_centers[img][t][3] = (float)y * R;
        g_centers[img][t][4] = (float)x * R;
    }
}

// -------------------------------------------------------------------------
// Fused assignment + segment accumulation. Spatial candidate pruning per
// tile (provably safe). Distance formula replicates the reference:
//   d = f2 + c2 - 2*dot   (argmin, first-index tie-break).
// Accumulation: warp shuffle-reduction per present candidate, then one
// lane-0 double atomic per value straight to global (no shared atomics).
// -------------------------------------------------------------------------
__global__ void __launch_bounds__(THREADS) k_assign(const float* __restrict__ X) {
    const int img = blockIdx.z;
    const int x0  = blockIdx.x * TDIM;
    const int y0  = blockIdx.y * TDIM;
    const int t   = threadIdx.x;
    const int lane = t & 31;
    const float R = ratiof();

    __shared__ float sC[KK][5];
    __shared__ float sC2[KK];
    __shared__ float sLB[KK];
    __shared__ float sUB[KK];
    __shared__ int   sCand[KK];
    __shared__ int   sNum;

    for (int i = t; i < KK*5; i += THREADS)
        (&sC[0][0])[i] = (&g_centers[img][0][0])[i];
    __syncthreads();

    if (t < KK) {
        float c0=sC[t][0], c1=sC[t][1], c2=sC[t][2], c3=sC[t][3], c4=sC[t][4];
        sC2[t] = (((c0*c0 + c1*c1) + c2*c2) + c3*c3) + c4*c4;
        float ya = (float)y0 * R;
        float yb = (float)(y0 + TDIM - 1) * R;
        float xa = (float)x0 * R;
        float xb = (float)(x0 + TDIM - 1) * R;
        float dymin = fmaxf(fmaxf(ya - c3, c3 - yb), 0.0f);
        float dxmin = fmaxf(fmaxf(xa - c4, c4 - xb), 0.0f);
        float dymax = fmaxf(fabsf(ya - c3), fabsf(yb - c3));
        float dxmax = fmaxf(fabsf(xa - c4), fabsf(xb - c4));
        sLB[t] = dymin*dymin + dxmin*dxmin;              // >= 0, color >= 0
        sUB[t] = dymax*dymax + dxmax*dxmax + 3.0f;       // + color max (<=3)
    }
    __syncthreads();
    if (t == 0) {
        float m = sUB[0];
        #pragma unroll
        for (int j = 1; j < KK; j++) m = fminf(m, sUB[j]);
        m += 1.0f;  // slack >> fp32 rounding of the distance formula
        int n = 0;
        for (int j = 0; j < KK; j++)
            if (sLB[j] <= m) sCand[n++] = j;             // ascending index order
        sNum = n;
    }
    __syncthreads();
    const int num = sNum;

    const int ty = t >> 3;
    const int xo = x0 + (t & 7) * PIXPT;
    const int y  = y0 + ty;
    const float ys = (float)y * R;

    size_t base = ((size_t)(img*3)*HH + y) * WW + xo;
    float4 r4 = *reinterpret_cast<const float4*>(X + base);
    float4 g4 = *reinterpret_cast<const float4*>(X + base + (size_t)HH*WW);
    float4 b4 = *reinterpret_cast<const float4*>(X + base + 2*(size_t)HH*WW);

    float rv[PIXPT] = {r4.x, r4.y, r4.z, r4.w};
    float gv[PIXPT] = {g4.x, g4.y, g4.z, g4.w};
    float bv[PIXPT] = {b4.x, b4.y, b4.z, b4.w};
    float xs[PIXPT], f2[PIXPT], best[PIXPT];
    int   bj[PIXPT];
    #pragma unroll
    for (int i = 0; i < PIXPT; i++) {
        xs[i]   = (float)(xo + i) * R;
        f2[i]   = (((rv[i]*rv[i] + gv[i]*gv[i]) + bv[i]*bv[i]) + ys*ys) + xs[i]*xs[i];
        best[i] = 3.0e38f;
        bj[i]   = 0;
    }

    for (int c = 0; c < num; c++) {
        int j = sCand[c];
        float c0=sC[j][0], c1=sC[j][1], c2=sC[j][2], c3=sC[j][3], c4=sC[j][4];
        float cc = sC2[j];
        #pragma unroll
        for (int i = 0; i < PIXPT; i++) {
            float dot = rv[i]*c0 + gv[i]*c1 + bv[i]*c2 + ys*c3 + xs[i]*c4;
            float v = (f2[i] + cc) - 2.0f*dot;
            if (v < best[i]) { best[i] = v; bj[i] = j; }   // strict <: first index wins
        }
    }

    // Warp-level aggregation: for each candidate present in this warp,
    // butterfly-reduce the 6 partial sums and have lane 0 add to global.
    for (int c = 0; c < num; c++) {
        int j = sCand[c];
        float pr=0.f, pg=0.f, pb=0.f, px=0.f, pc=0.f;
        #pragma unroll
        for (int i = 0; i < PIXPT; i++) {
            if (bj[i] == j) { pr+=rv[i]; pg+=gv[i]; pb+=bv[i]; px+=xs[i]; pc+=1.0f; }
        }
        unsigned m = __ballot_sync(0xffffffffu, pc > 0.0f);
        if (m == 0u) continue;           // uniform across warp
        float py = ys * pc;              // y contribution (row varies per thread)
        #pragma unroll
        for (int o = 16; o > 0; o >>= 1) {
            pr += __shfl_down_sync(0xffffffffu, pr, o);
            pg += __shfl_down_sync(0xffffffffu, pg, o);
            pb += __shfl_down_sync(0xffffffffu, pb, o);
            py += __shfl_down_sync(0xffffffffu, py, o);
            px += __shfl_down_sync(0xffffffffu, px, o);
            pc += __shfl_down_sync(0xffffffffu, pc, o);
        }
        if (lane == 0) {
            double* gs = &g_sums[img][j][0];
            atomicAdd(gs + 0, (double)pr);
            atomicAdd(gs + 1, (double)pg);
            atomicAdd(gs + 2, (double)pb);
            atomicAdd(gs + 3, (double)py);
            atomicAdd(gs + 4, (double)px);
            atomicAdd(gs + 5, (double)pc);
        }
    }
}

// -------------------------------------------------------------------------
// Center update: new_center = sums / max(count, 1); re-zero sums.
// -------------------------------------------------------------------------
__global__ void k_update() {
    int img = blockIdx.x;
    int t   = threadIdx.x;
    if (t < KK) {
        double cnt = g_sums[img][t][5];
        double m = fmax(cnt, 1.0);
        #pragma unroll
        for (int d = 0; d < 5; d++) {
            g_centers[img][t][d] = (float)(g_sums[img][t][d] / m);
            g_sums[img][t][d] = 0.0;
        }
        g_sums[img][t][5] = 0.0;
    }
}

// -------------------------------------------------------------------------
// Finalize: mean_rgb[c] = (1/N) * sum_seg segsum_c / max(cnt,1); then k.
// All-double. Re-zeroes g_sums for graph replay self-consistency.
// -------------------------------------------------------------------------
__global__ void k_final(float* __restrict__ out) {
    int img = blockIdx.x;
    int t   = threadIdx.x;
    __shared__ double sr[KK], sg[KK], sb[KK];
    if (t < KK) {
        double cnt = g_sums[img][t][5];
        double m = fmax(cnt, 1.0);
        sr[t] = g_sums[img][t][0] / m;
        sg[t] = g_sums[img][t][1] / m;
        sb[t] = g_sums[img][t][2] / m;
        #pragma unroll
        for (int d = 0; d < 6; d++) g_sums[img][t][d] = 0.0;
    }
    __syncthreads();
    if (t == 0) {
        double tr=0.0, tg=0.0, tb=0.0;
        for (int j = 0; j < KK; j++) { tr += sr[j]; tg += sg[j]; tb += sb[j]; }
        const double invN = 1.0 / (double)NPIX;
        double mr = tr * invN, mg = tg * invN, mb = tb * invN;
        double Drg = (mr-mg)*(mr-mg);
        double Drb = (mr-mb)*(mr-mb);
        double Dgb = (mb-mg)*(mb-mg);
        out[img] = (float)sqrt(Drg*Drg + Drb*Drb + Dgb*Dgb);
    }
}

// -------------------------------------------------------------------------
extern "C" void kernel_launch(void* const* d_in, const int* in_sizes, int n_in,
                              void* d_out, int out_size) {
    const float* X = (const float*)d_in[0];
    float* out = (float*)d_out;

    k_init<<<BATCH, 64>>>(X);
    dim3 grid(TILES, TILES, BATCH);
    for (int it = 0; it < NITERS; it++) {
        k_assign<<<grid, THREADS>>>(X);
        k_update<<<BATCH, 64>>>();
    }
    k_assign<<<grid, THREADS>>>(X);   // final labels + segment sums
    k_final<<<BATCH, 64>>>(out);
}

// round 4
// speedup vs baseline: 11.8497x; 1.6407x over previous
#include <cuda_runtime.h>
#include <math.h>

#define BATCH   16
#define HH      512
#define WW      512
#define NPIX    (HH*WW)
#define KK      50
#define NITERS  10

#define TDIM    32            // 32x32 pixel tile per block
#define PIXPT   8             // pixels per thread (along x)
#define THREADS 128           // 32 rows * 4 threads/row
#define TILES   (WW/TDIM)     // 16

__device__ float  g_centers[BATCH][KK][5];
__device__ double g_sums[BATCH][KK][6];   // r,g,b, y*ratio, x*ratio, count

__device__ __forceinline__ float ratiof() {
    // COMPACTNESS / sqrt(N/K), rounded to f32 exactly like the reference
    return (float)(10.0 / sqrt((double)NPIX / (double)KK));
}

// -------------------------------------------------------------------------
// Init: grid-sampled centers (n=8 grid, first 50), zero segment sums.
// -------------------------------------------------------------------------
__global__ void k_init(const float* __restrict__ X) {
    int img = blockIdx.x;
    int t   = threadIdx.x;
    double* s = &g_sums[img][0][0];
    for (int i = t; i < KK*6; i += blockDim.x) s[i] = 0.0;
    if (t < KK) {
        const float R = ratiof();
        int gi = t >> 3, gj = t & 7;
        int y = 64*gi + 32, x = 64*gj + 32;
        size_t base = ((size_t)(img*3)*HH + y) * WW + x;
        g_centers[img][t][0] = X[base];
        g_centers[img][t][1] = X[base + (size_t)HH*WW];
        g_centers[img][t][2] = X[base + 2*(size_t)HH*WW];
        g_centers[img][t][3] = (float)y * R;
        g_centers[img][t][4] = (float)x * R;
    }
}

// -------------------------------------------------------------------------
// Fused assignment + segment accumulation. Spatial candidate pruning per
// tile (provably safe). Distance formula replicates the reference:
//   d = f2 + c2 - 2*dot   (argmin, first-index tie-break).
// Aggregation: warp shuffle-reduction per present candidate, lane-0 double
// atomics straight to global. No shared atomics anywhere.
// -------------------------------------------------------------------------
__global__ void __launch_bounds__(THREADS) k_assign(const float* __restrict__ X) {
    const int img = blockIdx.z;
    const int x0  = blockIdx.x * TDIM;
    const int y0  = blockIdx.y * TDIM;
    const int t   = threadIdx.x;
    const int lane = t & 31;
    const float R = ratiof();

    __shared__ float sC[KK][5];
    __shared__ float sC2[KK];
    __shared__ float sLB[KK];
    __shared__ float sUB[KK];
    __shared__ int   sCand[KK];
    __shared__ int   sNum;

    for (int i = t; i < KK*5; i += THREADS)
        (&sC[0][0])[i] = (&g_centers[img][0][0])[i];
    __syncthreads();

    if (t < KK) {
        float c0=sC[t][0], c1=sC[t][1], c2=sC[t][2], c3=sC[t][3], c4=sC[t][4];
        sC2[t] = (((c0*c0 + c1*c1) + c2*c2) + c3*c3) + c4*c4;
        float ya = (float)y0 * R;
        float yb = (float)(y0 + TDIM - 1) * R;
        float xa = (float)x0 * R;
        float xb = (float)(x0 + TDIM - 1) * R;
        float dymin = fmaxf(fmaxf(ya - c3, c3 - yb), 0.0f);
        float dxmin = fmaxf(fmaxf(xa - c4, c4 - xb), 0.0f);
        float dymax = fmaxf(fabsf(ya - c3), fabsf(yb - c3));
        float dxmax = fmaxf(fabsf(xa - c4), fabsf(xb - c4));
        sLB[t] = dymin*dymin + dxmin*dxmin;              // >= 0, color >= 0
        sUB[t] = dymax*dymax + dxmax*dxmax + 3.0f;       // + color max (<=3)
    }
    __syncthreads();
    // Parallel pruning in warp 0: strided min + butterfly, then ordered
    // compaction via ballot/popc (ascending index order preserved).
    if (t < 32) {
        float m = 3.0e38f;
        for (int j = lane; j < KK; j += 32) m = fminf(m, sUB[j]);
        #pragma unroll
        for (int o = 16; o > 0; o >>= 1)
            m = fminf(m, __shfl_xor_sync(0xffffffffu, m, o));
        m += 1.0f;  // slack >> fp32 rounding of the distance formula
        int n = 0;
        for (int base = 0; base < KK; base += 32) {
            int j = base + lane;
            bool ok = (j < KK) && (sLB[j] <= m);
            unsigned bm = __ballot_sync(0xffffffffu, ok);
            if (ok) sCand[n + __popc(bm & ((1u << lane) - 1u))] = j;
            n += __popc(bm);
        }
        if (lane == 0) sNum = n;
    }
    __syncthreads();
    const int num = sNum;

    const int ty = t >> 2;                  // 4 threads per 32-px row
    const int xo = x0 + (t & 3) * PIXPT;
    const int y  = y0 + ty;
    const float ys = (float)y * R;

    size_t base = ((size_t)(img*3)*HH + y) * WW + xo;
    float4 rA = *reinterpret_cast<const float4*>(X + base);
    float4 rB = *reinterpret_cast<const float4*>(X + base + 4);
    float4 gA = *reinterpret_cast<const float4*>(X + base + (size_t)HH*WW);
    float4 gB = *reinterpret_cast<const float4*>(X + base + (size_t)HH*WW + 4);
    float4 bA = *reinterpret_cast<const float4*>(X + base + 2*(size_t)HH*WW);
    float4 bB = *reinterpret_cast<const float4*>(X + base + 2*(size_t)HH*WW + 4);

    float rv[PIXPT] = {rA.x,rA.y,rA.z,rA.w, rB.x,rB.y,rB.z,rB.w};
    float gv[PIXPT] = {gA.x,gA.y,gA.z,gA.w, gB.x,gB.y,gB.z,gB.w};
    float bv[PIXPT] = {bA.x,bA.y,bA.z,bA.w, bB.x,bB.y,bB.z,bB.w};
    float xs[PIXPT], f2[PIXPT], best[PIXPT];
    int   bj[PIXPT];
    #pragma unroll
    for (int i = 0; i < PIXPT; i++) {
        xs[i]   = (float)(xo + i) * R;
        f2[i]   = (((rv[i]*rv[i] + gv[i]*gv[i]) + bv[i]*bv[i]) + ys*ys) + xs[i]*xs[i];
        best[i] = 3.0e38f;
        bj[i]   = 0;
    }

    for (int c = 0; c < num; c++) {
        int j = sCand[c];
        float c0=sC[j][0], c1=sC[j][1], c2=sC[j][2], c3=sC[j][3], c4=sC[j][4];
        float cc = sC2[j];
        #pragma unroll
        for (int i = 0; i < PIXPT; i++) {
            float dot = rv[i]*c0 + gv[i]*c1 + bv[i]*c2 + ys*c3 + xs[i]*c4;
            float v = (f2[i] + cc) - 2.0f*dot;
            if (v < best[i]) { best[i] = v; bj[i] = j; }   // strict <: first index wins
        }
    }

    // Warp-level aggregation: for each candidate present in this warp,
    // butterfly-reduce the 6 partial sums and have lane 0 add to global.
    for (int c = 0; c < num; c++) {
        int j = sCand[c];
        float pr=0.f, pg=0.f, pb=0.f, px=0.f, pc=0.f;
        #pragma unroll
        for (int i = 0; i < PIXPT; i++) {
            if (bj[i] == j) { pr+=rv[i]; pg+=gv[i]; pb+=bv[i]; px+=xs[i]; pc+=1.0f; }
        }
        unsigned m = __ballot_sync(0xffffffffu, pc > 0.0f);
        if (m == 0u) continue;           // uniform across warp
        float py = ys * pc;              // y contribution (row varies per thread)
        #pragma unroll
        for (int o = 16; o > 0; o >>= 1) {
            pr += __shfl_down_sync(0xffffffffu, pr, o);
            pg += __shfl_down_sync(0xffffffffu, pg, o);
            pb += __shfl_down_sync(0xffffffffu, pb, o);
            py += __shfl_down_sync(0xffffffffu, py, o);
            px += __shfl_down_sync(0xffffffffu, px, o);
            pc += __shfl_down_sync(0xffffffffu, pc, o);
        }
        if (lane == 0) {
            double* gs = &g_sums[img][j][0];
            atomicAdd(gs + 0, (double)pr);
            atomicAdd(gs + 1, (double)pg);
            atomicAdd(gs + 2, (double)pb);
            atomicAdd(gs + 3, (double)py);
            atomicAdd(gs + 4, (double)px);
            atomicAdd(gs + 5, (double)pc);
        }
    }
}

// -------------------------------------------------------------------------
// Center update: new_center = sums / max(count, 1); re-zero sums.
// -------------------------------------------------------------------------
__global__ void k_update() {
    int img = blockIdx.x;
    int t   = threadIdx.x;
    if (t < KK) {
        double cnt = g_sums[img][t][5];
        double m = fmax(cnt, 1.0);
        #pragma unroll
        for (int d = 0; d < 5; d++) {
            g_centers[img][t][d] = (float)(g_sums[img][t][d] / m);
            g_sums[img][t][d] = 0.0;
        }
        g_sums[img][t][5] = 0.0;
    }
}

// -------------------------------------------------------------------------
// Finalize: mean_rgb[c] = (1/N) * sum_seg segsum_c / max(cnt,1); then k.
// All-double. Re-zeroes g_sums for graph replay self-consistency.
// -------------------------------------------------------------------------
__global__ void k_final(float* __restrict__ out) {
    int img = blockIdx.x;
    int t   = threadIdx.x;
    __shared__ double sr[KK], sg[KK], sb[KK];
    if (t < KK) {
        double cnt = g_sums[img][t][5];
        double m = fmax(cnt, 1.0);
        sr[t] = g_sums[img][t][0] / m;
        sg[t] = g_sums[img][t][1] / m;
        sb[t] = g_sums[img][t][2] / m;
        #pragma unroll
        for (int d = 0; d < 6; d++) g_sums[img][t][d] = 0.0;
    }
    __syncthreads();
    if (t == 0) {
        double tr=0.0, tg=0.0, tb=0.0;
        for (int j = 0; j < KK; j++) { tr += sr[j]; tg += sg[j]; tb += sb[j]; }
        const double invN = 1.0 / (double)NPIX;
        double mr = tr * invN, mg = tg * invN, mb = tb * invN;
        double Drg = (mr-mg)*(mr-mg);
        double Drb = (mr-mb)*(mr-mb);
        double Dgb = (mb-mg)*(mb-mg);
        out[img] = (float)sqrt(Drg*Drg + Drb*Drb + Dgb*Dgb);
    }
}

// -------------------------------------------------------------------------
extern "C" void kernel_launch(void* const* d_in, const int* in_sizes, int n_in,
                              void* d_out, int out_size) {
    const float* X = (const float*)d_in[0];
    float* out = (float*)d_out;

    k_init<<<BATCH, 64>>>(X);
    dim3 grid(TILES, TILES, BATCH);
    for (int it = 0; it < NITERS; it++) {
        k_assign<<<grid, THREADS>>>(X);
        k_update<<<BATCH, 64>>>();
    }
    k_assign<<<grid, THREADS>>>(X);   // final labels + segment sums
    k_final<<<BATCH, 64>>>(out);
}

// round 5
// speedup vs baseline: 13.1711x; 1.1115x over previous
#include <cuda_runtime.h>
#include <math.h>

#define BATCH   16
#define HH      512
#define WW      512
#define NPIX    (HH*WW)
#define KK      50
#define NITERS  10

#define TDIM    32            // 32x32 pixel tile per block
#define PIXPT   8             // pixels per thread (along x)
#define THREADS 128           // 32 rows * 4 threads/row
#define TILES   (WW/TDIM)     // 16

// Triple-buffered segment sums: r,g,b, y*ratio, x*ratio, count
__device__ double g_sums[3][BATCH][KK][6];

__device__ __forceinline__ float ratiof() {
    // COMPACTNESS / sqrt(N/K), rounded to f32 exactly like the reference
    return (float)(10.0 / sqrt((double)NPIX / (double)KK));
}

// -------------------------------------------------------------------------
// Fused: center update (from read buffer) + assignment + segment
// accumulation (into write buffer) + zeroing of the dead buffer.
// Distance formula replicates the reference:
//   d = f2 + c2 - 2*dot   (argmin, first-index tie-break).
// -------------------------------------------------------------------------
__global__ void __launch_bounds__(THREADS)
k_assign(const float* __restrict__ X, int rb, int wb, int zb, int first) {
    const int img = blockIdx.z;
    const int x0  = blockIdx.x * TDIM;
    const int y0  = blockIdx.y * TDIM;
    const int t   = threadIdx.x;
    const int lane = t & 31;
    const float R = ratiof();

    __shared__ float sC[KK][5];
    __shared__ float sC2[KK];
    __shared__ float sLB[KK];
    __shared__ float sUB[KK];
    __shared__ int   sCand[KK];

    // Inline center computation (identical arithmetic to old k_update)
    if (t < KK) {
        float c0, c1, c2, c3, c4;
        if (first) {
            int gi = t >> 3, gj = t & 7;
            int yy = 64*gi + 32, xx = 64*gj + 32;
            size_t base = ((size_t)(img*3)*HH + yy) * WW + xx;
            c0 = X[base];
            c1 = X[base + (size_t)HH*WW];
            c2 = X[base + 2*(size_t)HH*WW];
            c3 = (float)yy * R;
            c4 = (float)xx * R;
        } else {
            const double* s = &g_sums[rb][img][t][0];
            double m = fmax(s[5], 1.0);
            c0 = (float)(s[0] / m);
            c1 = (float)(s[1] / m);
            c2 = (float)(s[2] / m);
            c3 = (float)(s[3] / m);
            c4 = (float)(s[4] / m);
        }
        sC[t][0]=c0; sC[t][1]=c1; sC[t][2]=c2; sC[t][3]=c3; sC[t][4]=c4;
        sC2[t] = (((c0*c0 + c1*c1) + c2*c2) + c3*c3) + c4*c4;
        float ya = (float)y0 * R;
        float yb = (float)(y0 + TDIM - 1) * R;
        float xa = (float)x0 * R;
        float xb = (float)(x0 + TDIM - 1) * R;
        float dymin = fmaxf(fmaxf(ya - c3, c3 - yb), 0.0f);
        float dxmin = fmaxf(fmaxf(xa - c4, c4 - xb), 0.0f);
        float dymax = fmaxf(fabsf(ya - c3), fabsf(yb - c3));
        float dxmax = fmaxf(fabsf(xa - c4), fabsf(xb - c4));
        sLB[t] = dymin*dymin + dxmin*dxmin;              // >= 0, color >= 0
        sUB[t] = dymax*dymax + dxmax*dxmax + 3.0f;       // + color max (<=3)
    }
    // One designated block per image zeroes the dead buffer for iter it+2
    if (blockIdx.x == 0 && blockIdx.y == 0) {
        double* z = &g_sums[zb][img][0][0];
        for (int i = t; i < KK*6; i += THREADS) z[i] = 0.0;
    }
    __syncthreads();

    // Every warp redundantly prunes (no extra block barrier needed):
    // min-UB via butterfly, ordered compaction via ballot/popc.
    float m = 3.0e38f;
    for (int j = lane; j < KK; j += 32) m = fminf(m, sUB[j]);
    #pragma unroll
    for (int o = 16; o > 0; o >>= 1)
        m = fminf(m, __shfl_xor_sync(0xffffffffu, m, o));
    m += 1.0f;  // slack >> fp32 rounding of the distance formula
    int num = 0;
    #pragma unroll
    for (int b = 0; b < KK; b += 32) {
        int j = b + lane;
        bool ok = (j < KK) && (sLB[j] <= m);
        unsigned bm = __ballot_sync(0xffffffffu, ok);
        if (ok) sCand[num + __popc(bm & ((1u << lane) - 1u))] = j;
        num += __popc(bm);
    }
    __syncwarp();

    const int ty = t >> 2;                  // 4 threads per 32-px row
    const int xo = x0 + (t & 3) * PIXPT;
    const int y  = y0 + ty;
    const float ys = (float)y * R;

    size_t base = ((size_t)(img*3)*HH + y) * WW + xo;
    float4 rA = *reinterpret_cast<const float4*>(X + base);
    float4 rB = *reinterpret_cast<const float4*>(X + base + 4);
    float4 gA = *reinterpret_cast<const float4*>(X + base + (size_t)HH*WW);
    float4 gB = *reinterpret_cast<const float4*>(X + base + (size_t)HH*WW + 4);
    float4 bA = *reinterpret_cast<const float4*>(X + base + 2*(size_t)HH*WW);
    float4 bB = *reinterpret_cast<const float4*>(X + base + 2*(size_t)HH*WW + 4);

    float rv[PIXPT] = {rA.x,rA.y,rA.z,rA.w, rB.x,rB.y,rB.z,rB.w};
    float gv[PIXPT] = {gA.x,gA.y,gA.z,gA.w, gB.x,gB.y,gB.z,gB.w};
    float bv[PIXPT] = {bA.x,bA.y,bA.z,bA.w, bB.x,bB.y,bB.z,bB.w};
    float xs[PIXPT], f2[PIXPT], best[PIXPT];
    int   bj[PIXPT];
    #pragma unroll
    for (int i = 0; i < PIXPT; i++) {
        xs[i]   = (float)(xo + i) * R;
        f2[i]   = (((rv[i]*rv[i] + gv[i]*gv[i]) + bv[i]*bv[i]) + ys*ys) + xs[i]*xs[i];
        best[i] = 3.0e38f;
        bj[i]   = 0;
    }

    for (int c = 0; c < num; c++) {
        int j = sCand[c];
        float c0=sC[j][0], c1=sC[j][1], c2=sC[j][2], c3=sC[j][3], c4=sC[j][4];
        float cc = sC2[j];
        #pragma unroll
        for (int i = 0; i < PIXPT; i++) {
            float dot = rv[i]*c0 + gv[i]*c1 + bv[i]*c2 + ys*c3 + xs[i]*c4;
            float v = (f2[i] + cc) - 2.0f*dot;
            if (v < best[i]) { best[i] = v; bj[i] = j; }   // strict <: first index wins
        }
    }

    // Warp-level aggregation: per present candidate, 5 float butterfly
    // chains + integer REDUX for the count; lane 0 adds to global (f64).
    for (int c = 0; c < num; c++) {
        int j = sCand[c];
        float pr=0.f, pg=0.f, pb=0.f, px=0.f;
        int ipc = 0;
        #pragma unroll
        for (int i = 0; i < PIXPT; i++) {
            if (bj[i] == j) { pr+=rv[i]; pg+=gv[i]; pb+=bv[i]; px+=xs[i]; ipc++; }
        }
        unsigned pm = __ballot_sync(0xffffffffu, ipc > 0);
        if (pm == 0u) continue;           // uniform across warp
        float py = ys * (float)ipc;       // y contribution (row varies per thread)
        int cnt = __reduce_add_sync(0xffffffffu, ipc);
        #pragma unroll
        for (int o = 16; o > 0; o >>= 1) {
            pr += __shfl_down_sync(0xffffffffu, pr, o);
            pg += __shfl_down_sync(0xffffffffu, pg, o);
            pb += __shfl_down_sync(0xffffffffu, pb, o);
            py += __shfl_down_sync(0xffffffffu, py, o);
            px += __shfl_down_sync(0xffffffffu, px, o);
        }
        if (lane == 0) {
            double* gs = &g_sums[wb][img][j][0];
            atomicAdd(gs + 0, (double)pr);
            atomicAdd(gs + 1, (double)pg);
            atomicAdd(gs + 2, (double)pb);
            atomicAdd(gs + 3, (double)py);
            atomicAdd(gs + 4, (double)px);
            atomicAdd(gs + 5, (double)cnt);
        }
    }
}

// -------------------------------------------------------------------------
// Finalize: mean_rgb[c] = (1/N) * sum_seg segsum_c / max(cnt,1); then k.
// All-double. Re-zeroes buffers 1 and 2 for graph-replay self-consistency
// (buffer 0 is zeroed by the last k_assign launch).
// -------------------------------------------------------------------------
__global__ void k_final(float* __restrict__ out, int fb) {
    int img = blockIdx.x;
    int t   = threadIdx.x;
    __shared__ double sr[KK], sg[KK], sb[KK];
    if (t < KK) {
        const double* s = &g_sums[fb][img][t][0];
        double m = fmax(s[5], 1.0);
        sr[t] = s[0] / m;
        sg[t] = s[1] / m;
        sb[t] = s[2] / m;
    }
    __syncthreads();
    {   // zero buffers 1 and 2 for this image
        double* z1 = &g_sums[1][img][0][0];
        double* z2 = &g_sums[2][img][0][0];
        for (int i = t; i < KK*6; i += blockDim.x) { z1[i] = 0.0; z2[i] = 0.0; }
    }
    if (t == 0) {
        double tr=0.0, tg=0.0, tb=0.0;
        for (int j = 0; j < KK; j++) { tr += sr[j]; tg += sg[j]; tb += sb[j]; }
        const double invN = 1.0 / (double)NPIX;
        double mr = tr * invN, mg = tg * invN, mb = tb * invN;
        double Drg = (mr-mg)*(mr-mg);
        double Drb = (mr-mb)*(mr-mb);
        double Dgb = (mb-mg)*(mb-mg);
        out[img] = (float)sqrt(Drg*Drg + Drb*Drb + Dgb*Dgb);
    }
}

// -------------------------------------------------------------------------
// Launch schedule (triple buffer):
//   it reads S[it%3] (it=0: samples X), writes S[(it+1)%3], zeroes S[(it+2)%3]
//   Invariant: write buffer is always zero at launch; after k_final all
//   three buffers are zero again (graph replay safe).
// -------------------------------------------------------------------------
extern "C" void kernel_launch(void* const* d_in, const int* in_sizes, int n_in,
                              void* d_out, int out_size) {
    const float* X = (const float*)d_in[0];
    float* out = (float*)d_out;

    dim3 grid(TILES, TILES, BATCH);
    for (int it = 0; it <= NITERS; it++) {
        k_assign<<<grid, THREADS>>>(X, it % 3, (it + 1) % 3, (it + 2) % 3,
                                    it == 0 ? 1 : 0);
    }
    k_final<<<BATCH, 64>>>(out, (NITERS + 1) % 3);
}

// round 7
// speedup vs baseline: 13.4550x; 1.0216x over previous
#include <cuda_runtime.h>
#include <math.h>

#define BATCH   16
#define HH      512
#define WW      512
#define NPIX    (HH*WW)
#define KK      50
#define NITERS  10

#define TDIM    32            // 32x32 pixel tile per block
#define PIXPT   8             // pixels per thread (along x)
#define THREADS 128           // 32 rows * 4 threads/row
#define TILES   (WW/TDIM)     // 16

// Triple-buffered segment sums: r,g,b, y*ratio, x*ratio, count
__device__ double g_sums[3][BATCH][KK][6];

__device__ __forceinline__ float ratiof() {
    // COMPACTNESS / sqrt(N/K), rounded to f32 exactly like the reference
    return (float)(10.0 / sqrt((double)NPIX / (double)KK));
}

// -------------------------------------------------------------------------
// Fused: center update (from read buffer) + assignment + segment
// accumulation (into write buffer) + zeroing of the dead buffer.
// Distance formula replicates the reference:
//   d = f2 + c2 - 2*dot   (argmin, first-index tie-break).
// -------------------------------------------------------------------------
__global__ void __launch_bounds__(THREADS, 7)
k_assign(const float* __restrict__ X, int rb, int wb, int zb, int first) {
    const int img = blockIdx.z;
    const int x0  = blockIdx.x * TDIM;
    const int y0  = blockIdx.y * TDIM;
    const int t   = threadIdx.x;
    const int lane = t & 31;
    const float R = ratiof();

    __shared__ float sC[KK][5];
    __shared__ float sC2[KK];
    __shared__ float sLB[KK];
    __shared__ float sUB[KK];
    __shared__ int   sCand[KK];

    // Inline center computation; all-f32 arithmetic (no f64 divides).
    if (t < KK) {
        float c0, c1, c2, c3, c4;
        if (first) {
            int gi = t >> 3, gj = t & 7;
            int yy = 64*gi + 32, xx = 64*gj + 32;
            size_t base = ((size_t)(img*3)*HH + yy) * WW + xx;
            c0 = X[base];
            c1 = X[base + (size_t)HH*WW];
            c2 = X[base + 2*(size_t)HH*WW];
            c3 = (float)yy * R;
            c4 = (float)xx * R;
        } else {
            const double* s = &g_sums[rb][img][t][0];
            float inv = 1.0f / fmaxf((float)s[5], 1.0f);
            c0 = (float)s[0] * inv;
            c1 = (float)s[1] * inv;
            c2 = (float)s[2] * inv;
            c3 = (float)s[3] * inv;
            c4 = (float)s[4] * inv;
        }
        sC[t][0]=c0; sC[t][1]=c1; sC[t][2]=c2; sC[t][3]=c3; sC[t][4]=c4;
        sC2[t] = (((c0*c0 + c1*c1) + c2*c2) + c3*c3) + c4*c4;
        float ya = (float)y0 * R;
        float yb = (float)(y0 + TDIM - 1) * R;
        float xa = (float)x0 * R;
        float xb = (float)(x0 + TDIM - 1) * R;
        float dymin = fmaxf(fmaxf(ya - c3, c3 - yb), 0.0f);
        float dxmin = fmaxf(fmaxf(xa - c4, c4 - xb), 0.0f);
        float dymax = fmaxf(fabsf(ya - c3), fabsf(yb - c3));
        float dxmax = fmaxf(fabsf(xa - c4), fabsf(xb - c4));
        sLB[t] = dymin*dymin + dxmin*dxmin;              // >= 0, color >= 0
        sUB[t] = dymax*dymax + dxmax*dxmax + 3.0f;       // + color max (<=3)
    }
    // One designated block per image zeroes the dead buffer for iter it+2
    if (blockIdx.x == 0 && blockIdx.y == 0) {
        double* z = &g_sums[zb][img][0][0];
        for (int i = t; i < KK*6; i += THREADS) z[i] = 0.0;
    }
    __syncthreads();

    // Every warp redundantly prunes (no extra block barrier needed):
    // min-UB via butterfly, ordered compaction via ballot/popc.
    float m = 3.0e38f;
    for (int j = lane; j < KK; j += 32) m = fminf(m, sUB[j]);
    #pragma unroll
    for (int o = 16; o > 0; o >>= 1)
        m = fminf(m, __shfl_xor_sync(0xffffffffu, m, o));
    m += 1.0f;  // slack >> fp32 rounding of the distance formula
    int num = 0;
    #pragma unroll
    for (int b = 0; b < KK; b += 32) {
        int j = b + lane;
        bool ok = (j < KK) && (sLB[j] <= m);
        unsigned bm = __ballot_sync(0xffffffffu, ok);
        if (ok) sCand[num + __popc(bm & ((1u << lane) - 1u))] = j;
        num += __popc(bm);
    }
    __syncwarp();

    const int ty = t >> 2;                  // 4 threads per 32-px row
    const int xo = x0 + (t & 3) * PIXPT;
    const int y  = y0 + ty;
    const float ys = (float)y * R;

    size_t base = ((size_t)(img*3)*HH + y) * WW + xo;
    float4 rA = *reinterpret_cast<const float4*>(X + base);
    float4 rB = *reinterpret_cast<const float4*>(X + base + 4);
    float4 gA = *reinterpret_cast<const float4*>(X + base + (size_t)HH*WW);
    float4 gB = *reinterpret_cast<const float4*>(X + base + (size_t)HH*WW + 4);
    float4 bA = *reinterpret_cast<const float4*>(X + base + 2*(size_t)HH*WW);
    float4 bB = *reinterpret_cast<const float4*>(X + base + 2*(size_t)HH*WW + 4);

    float rv[PIXPT] = {rA.x,rA.y,rA.z,rA.w, rB.x,rB.y,rB.z,rB.w};
    float gv[PIXPT] = {gA.x,gA.y,gA.z,gA.w, gB.x,gB.y,gB.z,gB.w};
    float bv[PIXPT] = {bA.x,bA.y,bA.z,bA.w, bB.x,bB.y,bB.z,bB.w};
    float xs[PIXPT], f2[PIXPT], best[PIXPT];
    int   bj[PIXPT];
    #pragma unroll
    for (int i = 0; i < PIXPT; i++) {
        xs[i]   = (float)(xo + i) * R;
        f2[i]   = (((rv[i]*rv[i] + gv[i]*gv[i]) + bv[i]*bv[i]) + ys*ys) + xs[i]*xs[i];
        best[i] = 3.0e38f;
        bj[i]   = 0;
    }

    for (int c = 0; c < num; c++) {
        int j = sCand[c];
        float c0=sC[j][0], c1=sC[j][1], c2=sC[j][2], c3=sC[j][3], c4=sC[j][4];
        float cc = sC2[j];
        #pragma unroll
        for (int i = 0; i < PIXPT; i++) {
            float dot = rv[i]*c0 + gv[i]*c1 + bv[i]*c2 + ys*c3 + xs[i]*c4;
            float v = (f2[i] + cc) - 2.0f*dot;
            if (v < best[i]) { best[i] = v; bj[i] = j; }   // strict <: first index wins
        }
    }

    // Warp-level aggregation: per present candidate, 5 float butterfly
    // chains + integer REDUX for the count; lane 0 adds to global (f64).
    for (int c = 0; c < num; c++) {
        int j = sCand[c];
        float pr=0.f, pg=0.f, pb=0.f, px=0.f;
        int ipc = 0;
        #pragma unroll
        for (int i = 0; i < PIXPT; i++) {
            if (bj[i] == j) { pr+=rv[i]; pg+=gv[i]; pb+=bv[i]; px+=xs[i]; ipc++; }
        }
        unsigned pm = __ballot_sync(0xffffffffu, ipc > 0);
        if (pm == 0u) continue;           // uniform across warp
        float py = ys * (float)ipc;       // y contribution (row varies per thread)
        int cnt = __reduce_add_sync(0xffffffffu, ipc);
        #pragma unroll
        for (int o = 16; o > 0; o >>= 1) {
            pr += __shfl_down_sync(0xffffffffu, pr, o);
            pg += __shfl_down_sync(0xffffffffu, pg, o);
            pb += __shfl_down_sync(0xffffffffu, pb, o);
            py += __shfl_down_sync(0xffffffffu, py, o);
            px += __shfl_down_sync(0xffffffffu, px, o);
        }
        if (lane == 0) {
            double* gs = &g_sums[wb][img][j][0];
            atomicAdd(gs + 0, (double)pr);
            atomicAdd(gs + 1, (double)pg);
            atomicAdd(gs + 2, (double)pb);
            atomicAdd(gs + 3, (double)py);
            atomicAdd(gs + 4, (double)px);
            atomicAdd(gs + 5, (double)cnt);
        }
    }
}

// -------------------------------------------------------------------------
// Finalize: mean_rgb[c] = (1/N) * sum_seg segsum_c / max(cnt,1); then k.
// All-double. Re-zeroes buffers 1 and 2 for graph-replay self-consistency
// (buffer 0 is zeroed by the last k_assign launch).
// -------------------------------------------------------------------------
__global__ void k_final(float* __restrict__ out, int fb) {
    int img = blockIdx.x;
    int t   = threadIdx.x;
    __shared__ double sr[KK], sg[KK], sb[KK];
    if (t < KK) {
        const double* s = &g_sums[fb][img][t][0];
        double m = fmax(s[5], 1.0);
        sr[t] = s[0] / m;
        sg[t] = s[1] / m;
        sb[t] = s[2] / m;
    }
    __syncthreads();
    {   // zero buffers 1 and 2 for this image
        double* z1 = &g_sums[1][img][0][0];
        double* z2 = &g_sums[2][img][0][0];
        for (int i = t; i < KK*6; i += blockDim.x) { z1[i] = 0.0; z2[i] = 0.0; }
    }
    if (t == 0) {
        double tr=0.0, tg=0.0, tb=0.0;
        for (int j = 0; j < KK; j++) { tr += sr[j]; tg += sg[j]; tb += sb[j]; }
        const double invN = 1.0 / (double)NPIX;
        double mr = tr * invN, mg = tg * invN, mb = tb * invN;
        double Drg = (mr-mg)*(mr-mg);
        double Drb = (mr-mb)*(mr-mb);
        double Dgb = (mb-mg)*(mb-mg);
        out[img] = (float)sqrt(Drg*Drg + Drb*Drb + Dgb*Dgb);
    }
}

// -------------------------------------------------------------------------
// Launch schedule (triple buffer):
//   it reads S[it%3] (it=0: samples X), writes S[(it+1)%3], zeroes S[(it+2)%3]
//   Invariant: write buffer is always zero at launch; after k_final all
//   three buffers are zero again (graph replay safe).
// -------------------------------------------------------------------------
extern "C" void kernel_launch(void* const* d_in, const int* in_sizes, int n_in,
                              void* d_out, int out_size) {
    const float* X = (const float*)d_in[0];
    float* out = (float*)d_out;

    dim3 grid(TILES, TILES, BATCH);
    for (int it = 0; it <= NITERS; it++) {
        k_assign<<<grid, THREADS>>>(X, it % 3, (it + 1) % 3, (it + 2) % 3,
                                    it == 0 ? 1 : 0);
    }
    k_final<<<BATCH, 64>>>(out, (NITERS + 1) % 3);
}

// round 9
// speedup vs baseline: 15.8010x; 1.1744x over previous
#include <cuda_runtime.h>
#include <math.h>

#define BATCH   16
#define HH      512
#define WW      512
#define NPIX    (HH*WW)
#define KK      50
#define NITERS  10

#define TDIM    32            // 32x32 pixel tile per block
#define PIXPT   8             // pixels per thread (along x)
#define THREADS 128           // 32 rows * 4 threads/row; warp = 8 rows x 32 cols
#define TILES   (WW/TDIM)     // 16

// Triple-buffered segment sums: r,g,b, y*ratio, x*ratio, count
__device__ double g_sums[3][BATCH][KK][6];

__device__ __forceinline__ float ratiof() {
    // COMPACTNESS / sqrt(N/K), rounded to f32 exactly like the reference
    return (float)(10.0 / sqrt((double)NPIX / (double)KK));
}

// -------------------------------------------------------------------------
// Fused: center update (from read buffer) + assignment + segment
// accumulation (into write buffer) + zeroing of the dead buffer.
// Distance formula replicates the reference:
//   d = f2 + c2 - 2*dot   (argmin, first-index tie-break).
// Pruning: per-WARP bbox (8 rows x 32 cols) -> candidate bitmasks in
// uniform registers; iteration via ffs preserves ascending index order.
// -------------------------------------------------------------------------
__global__ void __launch_bounds__(THREADS, 7)
k_assign(const float* __restrict__ X, int rb, int wb, int zb, int first) {
    const int img = blockIdx.z;
    const int x0  = blockIdx.x * TDIM;
    const int y0  = blockIdx.y * TDIM;
    const int t   = threadIdx.x;
    const int lane = t & 31;
    const int wrp  = t >> 5;
    const float R = ratiof();

    __shared__ float sC[KK][5];
    __shared__ float sC2[KK];

    // Inline center computation; all-f32 arithmetic (no f64 divides).
    if (t < KK) {
        float c0, c1, c2, c3, c4;
        if (first) {
            int gi = t >> 3, gj = t & 7;
            int yy = 64*gi + 32, xx = 64*gj + 32;
            size_t base = ((size_t)(img*3)*HH + yy) * WW + xx;
            c0 = X[base];
            c1 = X[base + (size_t)HH*WW];
            c2 = X[base + 2*(size_t)HH*WW];
            c3 = (float)yy * R;
            c4 = (float)xx * R;
        } else {
            const double* s = &g_sums[rb][img][t][0];
            float inv = 1.0f / fmaxf((float)s[5], 1.0f);
            c0 = (float)s[0] * inv;
            c1 = (float)s[1] * inv;
            c2 = (float)s[2] * inv;
            c3 = (float)s[3] * inv;
            c4 = (float)s[4] * inv;
        }
        sC[t][0]=c0; sC[t][1]=c1; sC[t][2]=c2; sC[t][3]=c3; sC[t][4]=c4;
        sC2[t] = (((c0*c0 + c1*c1) + c2*c2) + c3*c3) + c4*c4;
    }
    // One designated block per image zeroes the dead buffer for iter it+2
    if (blockIdx.x == 0 && blockIdx.y == 0) {
        double* z = &g_sums[zb][img][0][0];
        for (int i = t; i < KK*6; i += THREADS) z[i] = 0.0;
    }
    __syncthreads();

    // Per-warp pruning over the warp's own 8-row x 32-col bbox.
    // Lane handles centers j = lane and j = lane+32; LB/UB from bbox;
    // min-UB butterfly; ballot -> two uniform candidate masks.
    const int ywa = y0 + 8*wrp;             // warp's first row
    float ya = (float)ywa * R;
    float yb = (float)(ywa + 7) * R;
    float xa = (float)x0 * R;
    float xb = (float)(x0 + TDIM - 1) * R;
    float lb0, lb1;
    float ubmin = 3.0e38f;
    {
        int j = lane;
        float c3 = sC[j][3], c4 = sC[j][4];
        float dymin = fmaxf(fmaxf(ya - c3, c3 - yb), 0.0f);
        float dxmin = fmaxf(fmaxf(xa - c4, c4 - xb), 0.0f);
        float dymax = fmaxf(fabsf(ya - c3), fabsf(yb - c3));
        float dxmax = fmaxf(fabsf(xa - c4), fabsf(xb - c4));
        lb0 = dymin*dymin + dxmin*dxmin;
        ubmin = dymax*dymax + dxmax*dxmax + 3.0f;   // + color max (<=3)
    }
    {
        int j = 32 + lane;
        if (j < KK) {
            float c3 = sC[j][3], c4 = sC[j][4];
            float dymin = fmaxf(fmaxf(ya - c3, c3 - yb), 0.0f);
            float dxmin = fmaxf(fmaxf(xa - c4, c4 - xb), 0.0f);
            float dymax = fmaxf(fabsf(ya - c3), fabsf(yb - c3));
            float dxmax = fmaxf(fabsf(xa - c4), fabsf(xb - c4));
            lb1 = dymin*dymin + dxmin*dxmin;
            ubmin = fminf(ubmin, dymax*dymax + dxmax*dxmax + 3.0f);
        } else {
            lb1 = 3.0e38f;
        }
    }
    #pragma unroll
    for (int o = 16; o > 0; o >>= 1)
        ubmin = fminf(ubmin, __shfl_xor_sync(0xffffffffu, ubmin, o));
    const float thr = ubmin + 1.0f;  // slack >> fp32 rounding of distance formula
    unsigned cm0 = __ballot_sync(0xffffffffu, lb0 <= thr);
    unsigned cm1 = __ballot_sync(0xffffffffu, (32 + lane < KK) && (lb1 <= thr));

    const int xo = x0 + (t & 3) * PIXPT;
    const int y  = ywa + ((t & 31) >> 2);   // same mapping as ty = t>>2
    const float ys = (float)y * R;

    size_t base = ((size_t)(img*3)*HH + y) * WW + xo;
    float4 rA = *reinterpret_cast<const float4*>(X + base);
    float4 rB = *reinterpret_cast<const float4*>(X + base + 4);
    float4 gA = *reinterpret_cast<const float4*>(X + base + (size_t)HH*WW);
    float4 gB = *reinterpret_cast<const float4*>(X + base + (size_t)HH*WW + 4);
    float4 bA = *reinterpret_cast<const float4*>(X + base + 2*(size_t)HH*WW);
    float4 bB = *reinterpret_cast<const float4*>(X + base + 2*(size_t)HH*WW + 4);

    float rv[PIXPT] = {rA.x,rA.y,rA.z,rA.w, rB.x,rB.y,rB.z,rB.w};
    float gv[PIXPT] = {gA.x,gA.y,gA.z,gA.w, gB.x,gB.y,gB.z,gB.w};
    float bv[PIXPT] = {bA.x,bA.y,bA.z,bA.w, bB.x,bB.y,bB.z,bB.w};
    float xs[PIXPT], f2[PIXPT], best[PIXPT];
    int   bj[PIXPT];
    #pragma unroll
    for (int i = 0; i < PIXPT; i++) {
        xs[i]   = (float)(xo + i) * R;
        f2[i]   = (((rv[i]*rv[i] + gv[i]*gv[i]) + bv[i]*bv[i]) + ys*ys) + xs[i]*xs[i];
        best[i] = 3.0e38f;
        bj[i]   = 0;
    }

    // Mainloop over warp-candidate masks (ascending j; uniform across warp).
    unsigned m0 = cm0, m1 = cm1;
    while (m0) {
        int j = __ffs(m0) - 1; m0 &= m0 - 1;
        float c0=sC[j][0], c1=sC[j][1], c2=sC[j][2], c3=sC[j][3], c4=sC[j][4];
        float cc = sC2[j];
        #pragma unroll
        for (int i = 0; i < PIXPT; i++) {
            float dot = rv[i]*c0 + gv[i]*c1 + bv[i]*c2 + ys*c3 + xs[i]*c4;
            float v = (f2[i] + cc) - 2.0f*dot;
            if (v < best[i]) { best[i] = v; bj[i] = j; }   // strict <: first index wins
        }
    }
    while (m1) {
        int j = (__ffs(m1) - 1) + 32; m1 &= m1 - 1;
        float c0=sC[j][0], c1=sC[j][1], c2=sC[j][2], c3=sC[j][3], c4=sC[j][4];
        float cc = sC2[j];
        #pragma unroll
        for (int i = 0; i < PIXPT; i++) {
            float dot = rv[i]*c0 + gv[i]*c1 + bv[i]*c2 + ys*c3 + xs[i]*c4;
            float v = (f2[i] + cc) - 2.0f*dot;
            if (v < best[i]) { best[i] = v; bj[i] = j; }
        }
    }

    // Epilogue: per present candidate, 5 float butterfly chains + integer
    // REDUX for the count; lane 0 adds to global (f64 atomics).
    m0 = cm0; m1 = cm1;
    for (int half = 0; half < 2; half++) {
        unsigned mm = half ? m1 : m0;
        int joff = half ? 32 : 0;
        while (mm) {
            int j = (__ffs(mm) - 1) + joff; mm &= mm - 1;
            float pr=0.f, pg=0.f, pb=0.f, px=0.f;
            int ipc = 0;
            #pragma unroll
            for (int i = 0; i < PIXPT; i++) {
                if (bj[i] == j) { pr+=rv[i]; pg+=gv[i]; pb+=bv[i]; px+=xs[i]; ipc++; }
            }
            unsigned pm = __ballot_sync(0xffffffffu, ipc > 0);
            if (pm == 0u) continue;           // uniform across warp
            float py = ys * (float)ipc;       // y contribution (row varies per thread)
            int cnt = __reduce_add_sync(0xffffffffu, ipc);
            #pragma unroll
            for (int o = 16; o > 0; o >>= 1) {
                pr += __shfl_down_sync(0xffffffffu, pr, o);
                pg += __shfl_down_sync(0xffffffffu, pg, o);
                pb += __shfl_down_sync(0xffffffffu, pb, o);
                py += __shfl_down_sync(0xffffffffu, py, o);
                px += __shfl_down_sync(0xffffffffu, px, o);
            }
            if (lane == 0) {
                double* gs = &g_sums[wb][img][j][0];
                atomicAdd(gs + 0, (double)pr);
                atomicAdd(gs + 1, (double)pg);
                atomicAdd(gs + 2, (double)pb);
                atomicAdd(gs + 3, (double)py);
                atomicAdd(gs + 4, (double)px);
                atomicAdd(gs + 5, (double)cnt);
            }
        }
    }
}

// -------------------------------------------------------------------------
// Finalize: mean_rgb[c] = (1/N) * sum_seg segsum_c / max(cnt,1); then k.
// All-double. Re-zeroes buffers 1 and 2 for graph-replay self-consistency
// (buffer 0 is zeroed by the last k_assign launch).
// -------------------------------------------------------------------------
__global__ void k_final(float* __restrict__ out, int fb) {
    int img = blockIdx.x;
    int t   = threadIdx.x;
    __shared__ double sr[KK], sg[KK], sb[KK];
    if (t < KK) {
        const double* s = &g_sums[fb][img][t][0];
        double m = fmax(s[5], 1.0);
        sr[t] = s[0] / m;
        sg[t] = s[1] / m;
        sb[t] = s[2] / m;
    }
    __syncthreads();
    {   // zero buffers 1 and 2 for this image
        double* z1 = &g_sums[1][img][0][0];
        double* z2 = &g_sums[2][img][0][0];
        for (int i = t; i < KK*6; i += blockDim.x) { z1[i] = 0.0; z2[i] = 0.0; }
    }
    if (t == 0) {
        double tr=0.0, tg=0.0, tb=0.0;
        for (int j = 0; j < KK; j++) { tr += sr[j]; tg += sg[j]; tb += sb[j]; }
        const double invN = 1.0 / (double)NPIX;
        double mr = tr * invN, mg = tg * invN, mb = tb * invN;
        double Drg = (mr-mg)*(mr-mg);
        double Drb = (mr-mb)*(mr-mb);
        double Dgb = (mb-mg)*(mb-mg);
        out[img] = (float)sqrt(Drg*Drg + Drb*Drb + Dgb*Dgb);
    }
}

// -------------------------------------------------------------------------
// Launch schedule (triple buffer):
//   it reads S[it%3] (it=0: samples X), writes S[(it+1)%3], zeroes S[(it+2)%3]
//   Invariant: write buffer is always zero at launch; after k_final all
//   three buffers are zero again (graph replay safe).
// -------------------------------------------------------------------------
extern "C" void kernel_launch(void* const* d_in, const int* in_sizes, int n_in,
                              void* d_out, int out_size) {
    const float* X = (const float*)d_in[0];
    float* out = (float*)d_out;

    dim3 grid(TILES, TILES, BATCH);
    for (int it = 0; it <= NITERS; it++) {
        k_assign<<<grid, THREADS>>>(X, it % 3, (it + 1) % 3, (it + 2) % 3,
                                    it == 0 ? 1 : 0);
    }
    k_final<<<BATCH, 64>>>(out, (NITERS + 1) % 3);
}